// round 6
// baseline (speedup 1.0000x reference)
#include <cuda_runtime.h>
#include <math.h>

// BinEmbedding: out[p] = emb_table[tok(x[p])]
//   tok = 0 if isnan(x), else clamp(count(bins <= x) - 1, 0) + 1
//
// x (B*L,) f32, bins (256,) f32, emb_table (257*64,) f32,
// out (B*L, 64) f32 = 268 MB written.
//
// Status: wall-clock write drain = 6.05 TB/s ~= 88% of the LTS chip cap;
// all store-path variants (STG / TMA / .cs) converge at ~44-47 us.
// R6: finer tiles (PPB 256, grid 4096) to cut wave-quantization tail,
// default-policy stores (drop .cs), same guard-free MLP-8 copy phase.

#define NUM_BINS 256
#define F4_PER_ROW 16                    // 64 floats / 4
#define THREADS 256
#define PPB 256                          // positions per block
#define COPY_ITERS (PPB * F4_PER_ROW / THREADS)   // 16
#define BATCH 8

__global__ __launch_bounds__(THREADS) void bin_embed_kernel(
    const float*  __restrict__ x,
    const float*  __restrict__ bins,
    const float4* __restrict__ emb4,     // (NUM_BINS+1) * 16 float4
    float4*       __restrict__ out)      // n_pos * 16 float4
{
    __shared__ float sbins[NUM_BINS];
    __shared__ int   stok[PPB];

    const int tid  = threadIdx.x;
    const int base = blockIdx.x * PPB;

    sbins[tid] = bins[tid];              // THREADS == NUM_BINS
    __syncthreads();

    // ---- Phase 1: one search per thread ----
    {
        float v = __ldg(&x[base + tid]);
        int c = 0;
        bool nn = isnan(v);
        #pragma unroll
        for (int s = NUM_BINS >> 1; s > 0; s >>= 1) {
            if (sbins[c + s - 1] <= v) c += s;
        }
        int i0 = c - 1; if (i0 < 0) i0 = 0;
        stok[tid] = nn ? 0 : i0 + 1;
    }
    __syncthreads();

    // ---- Phase 2: gather + coalesced stores, 8-wide independent batches ----
    // float4 element index = tid + i*THREADS; sub = tid & 15 invariant;
    // row advances by 16 per iteration.
    const int sub = tid & 15;
    int row       = tid >> 4;
    float4* outp  = out + (size_t)base * F4_PER_ROW + tid;

    #pragma unroll
    for (int b = 0; b < COPY_ITERS / BATCH; b++) {   // 2 batches
        int tok[BATCH];
        #pragma unroll
        for (int k = 0; k < BATCH; k++) tok[k] = stok[row + k * 16];

        float4 val[BATCH];
        #pragma unroll
        for (int k = 0; k < BATCH; k++)
            val[k] = __ldg(&emb4[tok[k] * F4_PER_ROW + sub]);

        #pragma unroll
        for (int k = 0; k < BATCH; k++)
            outp[(size_t)k * THREADS] = val[k];

        row  += BATCH * 16;
        outp += (size_t)BATCH * THREADS;
    }
}

extern "C" void kernel_launch(void* const* d_in, const int* in_sizes, int n_in,
                              void* d_out, int out_size)
{
    const float*  x    = (const float*)d_in[0];
    const float*  bins = (const float*)d_in[1];
    const float4* emb4 = (const float4*)d_in[2];
    float4* out = (float4*)d_out;

    int n_pos  = in_sizes[0];            // 1,048,576; divisible by PPB
    int blocks = n_pos / PPB;            // 4096

    bin_embed_kernel<<<blocks, THREADS>>>(x, bins, emb4, out);
}

// round 7
// speedup vs baseline: 1.0588x; 1.0588x over previous
#include <cuda_runtime.h>
#include <math.h>

// BinEmbedding: out[p] = emb_table[tok(x[p])]
//   tok = 0 if isnan(x), else clamp(count(bins <= x) - 1, 0) + 1
//
// x (B*L,) f32, bins (256,) f32, emb_table (257*64,) f32,
// out (B*L, 64) f32 = 268 MB written.
//
// Converged design: wall-clock drain = ~6.4 TB/s = LTS chip cap. R7 combines
// the two best measured settings: PPB 256 / grid 4096 (best wave balance)
// + streaming (.cs) stores (write-once output, keep L2 for the table).

#define NUM_BINS 256
#define F4_PER_ROW 16                    // 64 floats / 4
#define THREADS 256
#define PPB 256                          // positions per block
#define COPY_ITERS (PPB * F4_PER_ROW / THREADS)   // 16
#define BATCH 8

__global__ __launch_bounds__(THREADS) void bin_embed_kernel(
    const float*  __restrict__ x,
    const float*  __restrict__ bins,
    const float4* __restrict__ emb4,     // (NUM_BINS+1) * 16 float4
    float4*       __restrict__ out)      // n_pos * 16 float4
{
    __shared__ float sbins[NUM_BINS];
    __shared__ int   stok[PPB];

    const int tid  = threadIdx.x;
    const int base = blockIdx.x * PPB;

    sbins[tid] = bins[tid];              // THREADS == NUM_BINS
    __syncthreads();

    // ---- Phase 1: one search per thread ----
    {
        float v = __ldg(&x[base + tid]);
        int c = 0;
        bool nn = isnan(v);
        #pragma unroll
        for (int s = NUM_BINS >> 1; s > 0; s >>= 1) {
            if (sbins[c + s - 1] <= v) c += s;
        }
        int i0 = c - 1; if (i0 < 0) i0 = 0;
        stok[tid] = nn ? 0 : i0 + 1;
    }
    __syncthreads();

    // ---- Phase 2: gather + coalesced streaming stores, 8-wide batches ----
    // float4 element index = tid + i*THREADS; sub = tid & 15 invariant;
    // row advances by 16 per iteration.
    const int sub = tid & 15;
    int row       = tid >> 4;
    float4* outp  = out + (size_t)base * F4_PER_ROW + tid;

    #pragma unroll
    for (int b = 0; b < COPY_ITERS / BATCH; b++) {   // 2 batches
        int tok[BATCH];
        #pragma unroll
        for (int k = 0; k < BATCH; k++) tok[k] = stok[row + k * 16];

        float4 val[BATCH];
        #pragma unroll
        for (int k = 0; k < BATCH; k++)
            val[k] = __ldg(&emb4[tok[k] * F4_PER_ROW + sub]);

        #pragma unroll
        for (int k = 0; k < BATCH; k++)
            __stcs(outp + (size_t)k * THREADS, val[k]);

        row  += BATCH * 16;
        outp += (size_t)BATCH * THREADS;
    }
}

extern "C" void kernel_launch(void* const* d_in, const int* in_sizes, int n_in,
                              void* d_out, int out_size)
{
    const float*  x    = (const float*)d_in[0];
    const float*  bins = (const float*)d_in[1];
    const float4* emb4 = (const float4*)d_in[2];
    float4* out = (float4*)d_out;

    int n_pos  = in_sizes[0];            // 1,048,576; divisible by PPB
    int blocks = n_pos / PPB;            // 4096

    bin_embed_kernel<<<blocks, THREADS>>>(x, bins, emb4, out);
}